// round 15
// baseline (speedup 1.0000x reference)
#include <cuda_runtime.h>
#include <cuda_bf16.h>
#include <cuda_fp16.h>
#include <cstdint>

#define N_NODES 20000
#define N_EDGES 640000
#define HIDDEN 256
#define VOCAB 119
#define N_FEATS 9
#define MPAD 20096   // 157 * 128
#define EMB_N (N_FEATS * VOCAB * HIDDEN)   // 274176
#define WN (HIDDEN * HIDDEN)               // 65536

// ---------------- scratch (device globals; zero-initialized at load) ----------
__device__ __align__(16) __half g_h[MPAD * HIDDEN];         // node features, fp16
__device__ __align__(16) __half g_agg[MPAD * HIDDEN];       // attention out, fp16
__device__ __align__(16) __half g_w[3 * WN];   // q,k,v weights fp16
__device__ __align__(16) __half g_wo[WN];      // o weights fp16
__device__ __align__(16) __half g_embh[EMB_N]; // fp16 embedding tables
__device__ __align__(16) __half g_qh[MPAD * HIDDEN];        // fp16 Q (pre-scaled /16)
__device__ __align__(16) unsigned char g_k8[MPAD * HIDDEN]; // e4m3 K (x16)
__device__ __align__(16) __half g_vh[MPAD * HIDDEN];
__device__ int g_rowptr[N_NODES + 1];

// ---------------- PTX helpers ---------------------------------------------------
__device__ __forceinline__ uint32_t smem_u32(const void* p) {
    uint32_t a;
    asm("{ .reg .u64 t; cvta.to.shared.u64 t, %1; cvt.u32.u64 %0, t; }" : "=r"(a) : "l"(p));
    return a;
}
__device__ __forceinline__ void mma16816(float* d, const uint32_t* a,
                                         uint32_t b0, uint32_t b1) {
    asm volatile(
        "mma.sync.aligned.m16n8k16.row.col.f32.f16.f16.f32 "
        "{%0,%1,%2,%3}, {%4,%5,%6,%7}, {%8,%9}, {%0,%1,%2,%3};"
        : "+f"(d[0]), "+f"(d[1]), "+f"(d[2]), "+f"(d[3])
        : "r"(a[0]), "r"(a[1]), "r"(a[2]), "r"(a[3]), "r"(b0), "r"(b1));
}
__device__ __forceinline__ void ldm_x4(uint32_t* r, uint32_t addr) {
    asm volatile("ldmatrix.sync.aligned.m8n8.x4.shared.b16 {%0,%1,%2,%3}, [%4];"
                 : "=r"(r[0]), "=r"(r[1]), "=r"(r[2]), "=r"(r[3]) : "r"(addr));
}
__device__ __forceinline__ unsigned long long pack_dup(float x) {
    unsigned long long r;
    asm("mov.b64 %0, {%1, %1};" : "=l"(r) : "f"(x));
    return r;
}
__device__ __forceinline__ unsigned long long f2_to_ull(float2 v) {
    unsigned long long r;
    asm("mov.b64 %0, {%1, %2};" : "=l"(r) : "f"(v.x), "f"(v.y));
    return r;
}
__device__ __forceinline__ float2 ull_to_f2(unsigned long long v) {
    float2 r;
    asm("mov.b64 {%0, %1}, %2;" : "=f"(r.x), "=f"(r.y) : "l"(v));
    return r;
}
__device__ __forceinline__ unsigned long long fma2(unsigned long long a,
                                                   unsigned long long b,
                                                   unsigned long long c) {
    unsigned long long d;
    asm("fma.rn.f32x2 %0, %1, %2, %3;" : "=l"(d) : "l"(a), "l"(b), "l"(c));
    return d;
}
__device__ __forceinline__ __half2 e4m3x2_to_h2(uint32_t v) {
    uint32_t r;
    asm("cvt.rn.f16x2.e4m3x2 %0, %1;" : "=r"(r) : "h"((unsigned short)v));
    return *(__half2*)&r;
}
#define CP16(dst, src) \
    asm volatile("cp.async.cg.shared.global [%0], [%1], 16;" :: "r"(dst), "l"(src))
#define CP_COMMIT() asm volatile("cp.async.commit_group;" ::: "memory")
#define CP_WAIT0()  asm volatile("cp.async.wait_group 0;" ::: "memory")

// ---------------- fused prep: emb cvt + 4 weight cvts + rowptr ------------------
__global__ void prep_kernel(const float* __restrict__ emb,
                            const float* __restrict__ qw, const float* __restrict__ kw,
                            const float* __restrict__ vw, const float* __restrict__ ow,
                            const int* __restrict__ erow) {
    int i = blockIdx.x * 256 + threadIdx.x;
    if (i < EMB_N) {
        g_embh[i] = __float2half_rn(emb[i]);
        return;
    }
    i -= EMB_N;
    if (i < 4 * WN) {
        const int seg = i >> 16, j = i & (WN - 1);
        const float* src = (seg == 0) ? qw : (seg == 1) ? kw : (seg == 2) ? vw : ow;
        __half v = __float2half_rn(src[j]);
        if (seg == 3) g_wo[j] = v; else g_w[i] = v;
        return;
    }
    i -= 4 * WN;
    if (i <= N_NODES) {
        int lo = 0, hi = N_EDGES;
        while (lo < hi) {
            int mid = (lo + hi) >> 1;
            if (erow[mid] < i) lo = mid + 1; else hi = mid;
        }
        g_rowptr[i] = lo;
    }
}
#define PREP_TOTAL (EMB_N + 4 * WN + N_NODES + 1)

// ---------------- AtomEncoder: warp per node, uint4 gathers ---------------------
__global__ __launch_bounds__(256) void embed_kernel(const int* __restrict__ X) {
    const int wid = threadIdx.x >> 5, lane = threadIdx.x & 31;
    const int node = blockIdx.x * 8 + wid;
    int xi = (lane < N_FEATS) ? X[node * N_FEATS + lane] : 0;

    float acc[8];
#pragma unroll
    for (int j = 0; j < 8; j++) acc[j] = 0.f;
#pragma unroll
    for (int f = 0; f < N_FEATS; f++) {
        int idx = __shfl_sync(0xffffffffu, xi, f);
        uint4 t = *((const uint4*)(g_embh + (size_t)(f * VOCAB + idx) * HIDDEN) + lane);
        const __half2* tp = (const __half2*)&t;
#pragma unroll
        for (int h = 0; h < 4; h++) {
            float2 x = __half22float2(tp[h]);
            acc[2 * h + 0] += x.x;
            acc[2 * h + 1] += x.y;
        }
    }
    __half hv[8];
#pragma unroll
    for (int j = 0; j < 8; j++) hv[j] = __float2half_rn(acc[j]);
    *(uint4*)(g_h + (size_t)node * HIDDEN + lane * 8) = *(uint4*)hv;
}

// ---------------- HMMA GEMM: single-pass fp16, 64-K chunks, 1 sync/chunk --------
#define RSTRIDE 144
#define TILE_B (128 * RSTRIDE)          // 18432
#define BUF_B  (2 * TILE_B)             // 36864: A, B
#define SMEM_DYN (2 * BUF_B)            // 73728

__global__ __launch_bounds__(256, 2) void gemm_mma(
    const __half* __restrict__ A, const __half* __restrict__ W,
    const float* __restrict__ b0, const float* __restrict__ b1, const float* __restrict__ b2,
    __half* __restrict__ cQ, unsigned char* __restrict__ cK8, __half* __restrict__ cV,
    float* __restrict__ cF,
    float scaleQ, int M)
{
    extern __shared__ __align__(16) char sm[];
    const uint32_t sbase = smem_u32(sm);

    const int tid = threadIdx.x;
    const int wid = tid >> 5, lane = tid & 31;
    const int br = blockIdx.x * 128;
    const int sel = blockIdx.y >> 1;
    const int bc = (blockIdx.y & 1) * 128;
    const int wm = wid & 3, wn = wid >> 2;

    float acc[2][8][4];
#pragma unroll
    for (int mt = 0; mt < 2; mt++)
#pragma unroll
        for (int nt = 0; nt < 8; nt++)
#pragma unroll
            for (int i = 0; i < 4; i++) acc[mt][nt][i] = 0.f;

    const char* gA = (const char*)(A + (size_t)br * HIDDEN);
    const char* gB = (const char*)(W + (size_t)sel * WN + (size_t)bc * HIDDEN);

    const int rI[4] = {tid >> 3, (tid + 256) >> 3, (tid + 512) >> 3, (tid + 768) >> 3};
    const int uI    = tid & 7;

#define LOAD_CHUNK(ch, buf)                                                         \
    do {                                                                            \
        uint32_t sb_ = sbase + (buf) * BUF_B;                                       \
        _Pragma("unroll")                                                           \
        for (int s_ = 0; s_ < 4; s_++) {                                            \
            uint32_t so_ = (uint32_t)(rI[s_] * RSTRIDE + uI * 16);                  \
            size_t go_ = (size_t)rI[s_] * 512 + (ch) * 128 + uI * 16;               \
            CP16(sb_ + so_,          gA + go_);                                     \
            CP16(sb_ + TILE_B + so_, gB + go_);                                     \
        }                                                                           \
    } while (0)

    LOAD_CHUNK(0, 0);
    CP_COMMIT();

    const uint32_t aRow = (uint32_t)(wm * 32 + (lane & 15));
    const uint32_t aKoff = (uint32_t)((lane >> 4) << 4);
    const uint32_t bRow = (uint32_t)(wn * 64 + (lane & 7) + ((lane >> 4) << 3));
    const uint32_t bKoff = (uint32_t)(((lane >> 3) & 1) << 4);

    for (int ch = 0; ch < 4; ch++) {
        CP_WAIT0();
        __syncthreads();
        if (ch + 1 < 4) {
            LOAD_CHUNK(ch + 1, (ch + 1) & 1);
            CP_COMMIT();
        }
        const uint32_t sb = sbase + (ch & 1) * BUF_B;
#pragma unroll
        for (int ks = 0; ks < 4; ks++) {
            const uint32_t ko = ks * 32;
            uint32_t ah[2][4];
#pragma unroll
            for (int mt = 0; mt < 2; mt++) {
                uint32_t arow = (aRow + mt * 16) * RSTRIDE + ko + aKoff;
                ldm_x4(ah[mt], sb + arow);
            }
#pragma unroll
            for (int g = 0; g < 4; g++) {
                uint32_t brow = (bRow + g * 16) * RSTRIDE + ko + bKoff;
                uint32_t bm[4];
                ldm_x4(bm, sb + TILE_B + brow);
#pragma unroll
                for (int t = 0; t < 2; t++) {
                    const int nt = g * 2 + t;
#pragma unroll
                    for (int mt = 0; mt < 2; mt++)
                        mma16816(acc[mt][nt], ah[mt], bm[2 * t], bm[2 * t + 1]);
                }
            }
        }
    }
#undef LOAD_CHUNK

    // epilogue
    const float* bias = (sel == 0) ? b0 : (sel == 1) ? b1 : b2;
    const float scale = (sel == 0) ? scaleQ : 1.0f;
    const int g4 = lane >> 2;
#pragma unroll
    for (int mt = 0; mt < 2; mt++) {
#pragma unroll
        for (int half = 0; half < 2; half++) {
            int row = br + wm * 32 + mt * 16 + g4 + half * 8;
            if (row < M) {
#pragma unroll
                for (int nt = 0; nt < 8; nt++) {
                    int col = bc + wn * 64 + nt * 8 + (lane & 3) * 2;
                    float x0 = (acc[mt][nt][half * 2 + 0] + bias[col + 0]) * scale;
                    float x1 = (acc[mt][nt][half * 2 + 1] + bias[col + 1]) * scale;
                    if (cF) {
                        *(float2*)(cF + (size_t)row * HIDDEN + col) = make_float2(x0, x1);
                    } else if (sel == 1) {
                        unsigned short r8;
                        asm("cvt.rn.satfinite.e4m3x2.f32 %0, %1, %2;"
                            : "=h"(r8) : "f"(x1 * 16.f), "f"(x0 * 16.f));
                        *(unsigned short*)(cK8 + (size_t)row * HIDDEN + col) = r8;
                    } else {
                        __half* dstH = (sel == 0) ? cQ : cV;
                        *(__half2*)(dstH + (size_t)row * HIDDEN + col) =
                            __floats2half2_rn(x0, x1);
                    }
                }
            }
        }
    }
}

// ---------------- fused SDDMM + softmax + SPMM ----------------------------------
// Warp per node (grid 2500). Lane = (edge-slot, head): head = lane&7,
// sub = lane>>3 -> 4 edges per warp-iteration. Each lane computes its head's
// full 32-dim dot in-register (no shuffles in the hot loop); cross-sub combine
// once per node. K e4m3, V fp16, f32x2 packed accumulation.
__global__ __launch_bounds__(256) void attn_kernel(const int* __restrict__ ecol) {
    const int wid = threadIdx.x >> 5, lane = threadIdx.x & 31;
    const int node = blockIdx.x * 8 + wid;
    const int head = lane & 7, sub = lane >> 3;

    const int start = g_rowptr[node];
    const int end = g_rowptr[node + 1];

    if (start >= end) {
        if (sub == 0) {
            uint4* dst = (uint4*)(g_agg + (size_t)node * HIDDEN + head * 32);
            const uint4 zz = make_uint4(0, 0, 0, 0);
            dst[0] = zz; dst[1] = zz; dst[2] = zz; dst[3] = zz;
        }
        return;
    }
    const int last = end - 1;

    // Q for this lane's head: 32 dims = 4 uint4 = 16 half2
    uint4 q4[4];
    {
        const uint4* qp = (const uint4*)(g_qh + (size_t)node * HIDDEN + head * 32);
        q4[0] = qp[0]; q4[1] = qp[1]; q4[2] = qp[2]; q4[3] = qp[3];
    }
    const __half2* qh = (const __half2*)q4;

    float z = 0.f;
    unsigned long long acc[16];
#pragma unroll
    for (int i = 0; i < 16; i++) acc[i] = 0ull;

#define LDGRP(K0, K1, VV, e)                                                        \
    do {                                                                            \
        int c_ = ecol[min((e) + sub, last)];                                        \
        const uint4* kp_ = (const uint4*)(g_k8 + (size_t)c_ * HIDDEN + head * 32);  \
        K0 = kp_[0]; K1 = kp_[1];                                                   \
        const uint4* vp_ = (const uint4*)(g_vh + (size_t)c_ * HIDDEN + head * 32);  \
        VV[0] = vp_[0]; VV[1] = vp_[1]; VV[2] = vp_[2]; VV[3] = vp_[3];             \
    } while (0)

#define CONSUME(K0, K1, VV, eb)                                                     \
    do {                                                                            \
        __half2 s0 = __hmul2(qh[0], e4m3x2_to_h2((K0).x));                          \
        __half2 s1 = __hmul2(qh[1], e4m3x2_to_h2((K0).x >> 16));                    \
        s0 = __hfma2(qh[2],  e4m3x2_to_h2((K0).y),       s0);                       \
        s1 = __hfma2(qh[3],  e4m3x2_to_h2((K0).y >> 16), s1);                       \
        s0 = __hfma2(qh[4],  e4m3x2_to_h2((K0).z),       s0);                       \
        s1 = __hfma2(qh[5],  e4m3x2_to_h2((K0).z >> 16), s1);                       \
        s0 = __hfma2(qh[6],  e4m3x2_to_h2((K0).w),       s0);                       \
        s1 = __hfma2(qh[7],  e4m3x2_to_h2((K0).w >> 16), s1);                       \
        s0 = __hfma2(qh[8],  e4m3x2_to_h2((K1).x),       s0);                       \
        s1 = __hfma2(qh[9],  e4m3x2_to_h2((K1).x >> 16), s1);                       \
        s0 = __hfma2(qh[10], e4m3x2_to_h2((K1).y),       s0);                       \
        s1 = __hfma2(qh[11], e4m3x2_to_h2((K1).y >> 16), s1);                       \
        s0 = __hfma2(qh[12], e4m3x2_to_h2((K1).z),       s0);                       \
        s1 = __hfma2(qh[13], e4m3x2_to_h2((K1).z >> 16), s1);                       \
        s0 = __hfma2(qh[14], e4m3x2_to_h2((K1).w),       s0);                       \
        s1 = __hfma2(qh[15], e4m3x2_to_h2((K1).w >> 16), s1);                       \
        __half2 st = __hadd2(s0, s1);                                               \
        float p = __low2float(st) + __high2float(st);                               \
        float w = ((eb) + sub < end) ? __expf(p) : 0.f;                             \
        z += w;                                                                     \
        unsigned long long wp = pack_dup(w);                                        \
        const __half2* vh_ = (const __half2*)(VV);                                  \
        _Pragma("unroll")                                                           \
        for (int i_ = 0; i_ < 16; i_++)                                             \
            acc[i_] = fma2(wp, f2_to_ull(__half22float2(vh_[i_])), acc[i_]);        \
    } while (0)

    uint4 kA0, kA1, vA[4], kB0, kB1, vB[4];
    LDGRP(kA0, kA1, vA, start);
    LDGRP(kB0, kB1, vB, start + 4);

    for (int e = start; e < end; e += 8) {
        CONSUME(kA0, kA1, vA, e);
        LDGRP(kA0, kA1, vA, e + 8);
        if (e + 4 < end) {
            CONSUME(kB0, kB1, vB, e + 4);
            LDGRP(kB0, kB1, vB, e + 12);
        }
    }
#undef CONSUME
#undef LDGRP

    // combine across the 4 edge-slots (sub): xor 8, then xor 16
#pragma unroll
    for (int ofs = 8; ofs <= 16; ofs <<= 1) {
        z += __shfl_xor_sync(0xffffffffu, z, ofs);
#pragma unroll
        for (int i = 0; i < 16; i++) {
            float2 t = ull_to_f2(acc[i]);
            t.x += __shfl_xor_sync(0xffffffffu, t.x, ofs);
            t.y += __shfl_xor_sync(0xffffffffu, t.y, ofs);
            acc[i] = f2_to_ull(t);
        }
    }

    if (sub == 0) {
        const float inv = 1.f / z;
        __half o[32];
#pragma unroll
        for (int i = 0; i < 16; i++) {
            float2 t = ull_to_f2(acc[i]);
            o[2 * i + 0] = __float2half_rn(t.x * inv);
            o[2 * i + 1] = __float2half_rn(t.y * inv);
        }
        uint4* dst = (uint4*)(g_agg + (size_t)node * HIDDEN + head * 32);
        const uint4* src = (const uint4*)o;
        dst[0] = src[0]; dst[1] = src[1]; dst[2] = src[2]; dst[3] = src[3];
    }
}

// ---------------- launch --------------------------------------------------------
extern "C" void kernel_launch(void* const* d_in, const int* in_sizes, int n_in,
                              void* d_out, int out_size) {
    const int*   X    = (const int*)d_in[0];
    const int*   erow = (const int*)d_in[1];
    const int*   ecol = (const int*)d_in[2];
    const float* emb  = (const float*)d_in[3];
    const float* q_w  = (const float*)d_in[4];
    const float* q_b  = (const float*)d_in[5];
    const float* k_w  = (const float*)d_in[6];
    const float* k_b  = (const float*)d_in[7];
    const float* v_w  = (const float*)d_in[8];
    const float* v_b  = (const float*)d_in[9];
    const float* o_w  = (const float*)d_in[10];
    const float* o_b  = (const float*)d_in[11];
    float* out = (float*)d_out;

    __half *ph, *agg, *pw, *pwo, *pqh, *pvh;
    unsigned char *pk8;
    cudaGetSymbolAddress((void**)&ph,  g_h);
    cudaGetSymbolAddress((void**)&agg, g_agg);
    cudaGetSymbolAddress((void**)&pw,  g_w);
    cudaGetSymbolAddress((void**)&pwo, g_wo);
    cudaGetSymbolAddress((void**)&pqh, g_qh);
    cudaGetSymbolAddress((void**)&pk8, g_k8);
    cudaGetSymbolAddress((void**)&pvh, g_vh);

    cudaFuncSetAttribute(gemm_mma, cudaFuncAttributeMaxDynamicSharedMemorySize, SMEM_DYN);

    prep_kernel<<<(PREP_TOTAL + 255) / 256, 256>>>(emb, q_w, k_w, v_w, o_w, erow);
    embed_kernel<<<2500, 256>>>(X);

    const float qscale = 0.17677669529663687f / 16.f;   // HEAD_DIM^-0.5 / 16 (K is x16)
    gemm_mma<<<dim3(157, 6), 256, SMEM_DYN>>>(ph, pw,
                                              q_b, k_b, v_b, pqh, pk8, pvh, nullptr,
                                              qscale, N_NODES);

    attn_kernel<<<2500, 256>>>(ecol);

    gemm_mma<<<dim3(157, 2), 256, SMEM_DYN>>>(agg, pwo,
                                              o_b, o_b, o_b, nullptr, nullptr, nullptr, out,
                                              1.0f, N_NODES);
}

// round 16
// speedup vs baseline: 1.2337x; 1.2337x over previous
#include <cuda_runtime.h>
#include <cuda_bf16.h>
#include <cuda_fp16.h>
#include <cstdint>

#define N_NODES 20000
#define N_EDGES 640000
#define HIDDEN 256
#define VOCAB 119
#define N_FEATS 9
#define MPAD 20096   // 157 * 128
#define EMB_N (N_FEATS * VOCAB * HIDDEN)   // 274176
#define WN (HIDDEN * HIDDEN)               // 65536

// ---------------- scratch (device globals; zero-initialized at load) ----------
__device__ __align__(16) __half g_h[MPAD * HIDDEN];         // node features, fp16
__device__ __align__(16) __half g_agg[MPAD * HIDDEN];       // attention out, fp16
__device__ __align__(16) __half g_w[3 * WN];   // q,k,v weights fp16
__device__ __align__(16) __half g_wo[WN];      // o weights fp16
__device__ __align__(16) __half g_embh[EMB_N]; // fp16 embedding tables
__device__ __align__(16) __half g_qh[MPAD * HIDDEN];        // fp16 Q (pre-scaled /16)
__device__ __align__(16) unsigned char g_k8[MPAD * HIDDEN]; // e4m3 K (x16)
__device__ __align__(16) __half g_vh[MPAD * HIDDEN];
__device__ int g_rowptr[N_NODES + 1];

// ---------------- PTX helpers ---------------------------------------------------
__device__ __forceinline__ uint32_t smem_u32(const void* p) {
    uint32_t a;
    asm("{ .reg .u64 t; cvta.to.shared.u64 t, %1; cvt.u32.u64 %0, t; }" : "=r"(a) : "l"(p));
    return a;
}
__device__ __forceinline__ void mma16816(float* d, const uint32_t* a,
                                         uint32_t b0, uint32_t b1) {
    asm volatile(
        "mma.sync.aligned.m16n8k16.row.col.f32.f16.f16.f32 "
        "{%0,%1,%2,%3}, {%4,%5,%6,%7}, {%8,%9}, {%0,%1,%2,%3};"
        : "+f"(d[0]), "+f"(d[1]), "+f"(d[2]), "+f"(d[3])
        : "r"(a[0]), "r"(a[1]), "r"(a[2]), "r"(a[3]), "r"(b0), "r"(b1));
}
__device__ __forceinline__ void ldm_x4(uint32_t* r, uint32_t addr) {
    asm volatile("ldmatrix.sync.aligned.m8n8.x4.shared.b16 {%0,%1,%2,%3}, [%4];"
                 : "=r"(r[0]), "=r"(r[1]), "=r"(r[2]), "=r"(r[3]) : "r"(addr));
}
__device__ __forceinline__ unsigned long long pack_dup(float x) {
    unsigned long long r;
    asm("mov.b64 %0, {%1, %1};" : "=l"(r) : "f"(x));
    return r;
}
__device__ __forceinline__ unsigned long long f2_to_ull(float2 v) {
    unsigned long long r;
    asm("mov.b64 %0, {%1, %2};" : "=l"(r) : "f"(v.x), "f"(v.y));
    return r;
}
__device__ __forceinline__ float2 ull_to_f2(unsigned long long v) {
    float2 r;
    asm("mov.b64 {%0, %1}, %2;" : "=f"(r.x), "=f"(r.y) : "l"(v));
    return r;
}
__device__ __forceinline__ unsigned long long fma2(unsigned long long a,
                                                   unsigned long long b,
                                                   unsigned long long c) {
    unsigned long long d;
    asm("fma.rn.f32x2 %0, %1, %2, %3;" : "=l"(d) : "l"(a), "l"(b), "l"(c));
    return d;
}
__device__ __forceinline__ __half2 e4m3x2_to_h2(uint32_t v) {
    uint32_t r;
    asm("cvt.rn.f16x2.e4m3x2 %0, %1;" : "=r"(r) : "h"((unsigned short)v));
    return *(__half2*)&r;
}
#define CP16(dst, src) \
    asm volatile("cp.async.cg.shared.global [%0], [%1], 16;" :: "r"(dst), "l"(src))
#define CP_COMMIT() asm volatile("cp.async.commit_group;" ::: "memory")
#define CP_WAIT0()  asm volatile("cp.async.wait_group 0;" ::: "memory")

// ---------------- fused prep (4-wide): emb cvt + weight cvts + rowptr -----------
// vector part: (EMB_N + 4*WN)/4 threads, each converts 4 floats -> 4 halves.
#define PREP_VEC ((EMB_N + 4 * WN) / 4)
#define PREP_TOTAL (PREP_VEC + N_NODES + 1)

__global__ void prep_kernel(const float* __restrict__ emb,
                            const float* __restrict__ qw, const float* __restrict__ kw,
                            const float* __restrict__ vw, const float* __restrict__ ow,
                            const int* __restrict__ erow) {
    int i = blockIdx.x * 256 + threadIdx.x;
    if (i < PREP_VEC) {
        const int j = i * 4;
        const float* src;
        __half* dst;
        if (j < EMB_N) {
            src = emb + j;
            dst = g_embh + j;
        } else {
            const int k = j - EMB_N;
            const int seg = k >> 16, jj = k & (WN - 1);
            src = ((seg == 0) ? qw : (seg == 1) ? kw : (seg == 2) ? vw : ow) + jj;
            dst = (seg == 3) ? (g_wo + jj) : (g_w + k);
        }
        float4 x = *(const float4*)src;
        __half h[4];
        h[0] = __float2half_rn(x.x);
        h[1] = __float2half_rn(x.y);
        h[2] = __float2half_rn(x.z);
        h[3] = __float2half_rn(x.w);
        *(uint2*)dst = *(uint2*)h;
        return;
    }
    i -= PREP_VEC;
    if (i <= N_NODES) {
        int lo = 0, hi = N_EDGES;
        while (lo < hi) {
            int mid = (lo + hi) >> 1;
            if (erow[mid] < i) lo = mid + 1; else hi = mid;
        }
        g_rowptr[i] = lo;
    }
}

// ---------------- AtomEncoder: warp per node, uint4 gathers ---------------------
__global__ __launch_bounds__(256) void embed_kernel(const int* __restrict__ X) {
    const int wid = threadIdx.x >> 5, lane = threadIdx.x & 31;
    const int node = blockIdx.x * 8 + wid;
    int xi = (lane < N_FEATS) ? X[node * N_FEATS + lane] : 0;

    float acc[8];
#pragma unroll
    for (int j = 0; j < 8; j++) acc[j] = 0.f;
#pragma unroll
    for (int f = 0; f < N_FEATS; f++) {
        int idx = __shfl_sync(0xffffffffu, xi, f);
        uint4 t = *((const uint4*)(g_embh + (size_t)(f * VOCAB + idx) * HIDDEN) + lane);
        const __half2* tp = (const __half2*)&t;
#pragma unroll
        for (int h = 0; h < 4; h++) {
            float2 x = __half22float2(tp[h]);
            acc[2 * h + 0] += x.x;
            acc[2 * h + 1] += x.y;
        }
    }
    __half hv[8];
#pragma unroll
    for (int j = 0; j < 8; j++) hv[j] = __float2half_rn(acc[j]);
    *(uint4*)(g_h + (size_t)node * HIDDEN + lane * 8) = *(uint4*)hv;
}

// ---------------- HMMA GEMM: single-pass fp16, 64-K chunks, 1 sync/chunk --------
#define RSTRIDE 144
#define TILE_B (128 * RSTRIDE)          // 18432
#define BUF_B  (2 * TILE_B)             // 36864: A, B
#define SMEM_DYN (2 * BUF_B)            // 73728

__global__ __launch_bounds__(256, 2) void gemm_mma(
    const __half* __restrict__ A, const __half* __restrict__ W,
    const float* __restrict__ b0, const float* __restrict__ b1, const float* __restrict__ b2,
    __half* __restrict__ cQ, unsigned char* __restrict__ cK8, __half* __restrict__ cV,
    float* __restrict__ cF,
    float scaleQ, int M)
{
    extern __shared__ __align__(16) char sm[];
    const uint32_t sbase = smem_u32(sm);

    const int tid = threadIdx.x;
    const int wid = tid >> 5, lane = tid & 31;
    const int br = blockIdx.x * 128;
    const int sel = blockIdx.y >> 1;
    const int bc = (blockIdx.y & 1) * 128;
    const int wm = wid & 3, wn = wid >> 2;

    float acc[2][8][4];
#pragma unroll
    for (int mt = 0; mt < 2; mt++)
#pragma unroll
        for (int nt = 0; nt < 8; nt++)
#pragma unroll
            for (int i = 0; i < 4; i++) acc[mt][nt][i] = 0.f;

    const char* gA = (const char*)(A + (size_t)br * HIDDEN);
    const char* gB = (const char*)(W + (size_t)sel * WN + (size_t)bc * HIDDEN);

    const int rI[4] = {tid >> 3, (tid + 256) >> 3, (tid + 512) >> 3, (tid + 768) >> 3};
    const int uI    = tid & 7;

#define LOAD_CHUNK(ch, buf)                                                         \
    do {                                                                            \
        uint32_t sb_ = sbase + (buf) * BUF_B;                                       \
        _Pragma("unroll")                                                           \
        for (int s_ = 0; s_ < 4; s_++) {                                            \
            uint32_t so_ = (uint32_t)(rI[s_] * RSTRIDE + uI * 16);                  \
            size_t go_ = (size_t)rI[s_] * 512 + (ch) * 128 + uI * 16;               \
            CP16(sb_ + so_,          gA + go_);                                     \
            CP16(sb_ + TILE_B + so_, gB + go_);                                     \
        }                                                                           \
    } while (0)

    LOAD_CHUNK(0, 0);
    CP_COMMIT();

    const uint32_t aRow = (uint32_t)(wm * 32 + (lane & 15));
    const uint32_t aKoff = (uint32_t)((lane >> 4) << 4);
    const uint32_t bRow = (uint32_t)(wn * 64 + (lane & 7) + ((lane >> 4) << 3));
    const uint32_t bKoff = (uint32_t)(((lane >> 3) & 1) << 4);

    for (int ch = 0; ch < 4; ch++) {
        CP_WAIT0();
        __syncthreads();
        if (ch + 1 < 4) {
            LOAD_CHUNK(ch + 1, (ch + 1) & 1);
            CP_COMMIT();
        }
        const uint32_t sb = sbase + (ch & 1) * BUF_B;
#pragma unroll
        for (int ks = 0; ks < 4; ks++) {
            const uint32_t ko = ks * 32;
            uint32_t ah[2][4];
#pragma unroll
            for (int mt = 0; mt < 2; mt++) {
                uint32_t arow = (aRow + mt * 16) * RSTRIDE + ko + aKoff;
                ldm_x4(ah[mt], sb + arow);
            }
#pragma unroll
            for (int g = 0; g < 4; g++) {
                uint32_t brow = (bRow + g * 16) * RSTRIDE + ko + bKoff;
                uint32_t bm[4];
                ldm_x4(bm, sb + TILE_B + brow);
#pragma unroll
                for (int t = 0; t < 2; t++) {
                    const int nt = g * 2 + t;
#pragma unroll
                    for (int mt = 0; mt < 2; mt++)
                        mma16816(acc[mt][nt], ah[mt], bm[2 * t], bm[2 * t + 1]);
                }
            }
        }
    }
#undef LOAD_CHUNK

    // epilogue
    const float* bias = (sel == 0) ? b0 : (sel == 1) ? b1 : b2;
    const float scale = (sel == 0) ? scaleQ : 1.0f;
    const int g4 = lane >> 2;
#pragma unroll
    for (int mt = 0; mt < 2; mt++) {
#pragma unroll
        for (int half = 0; half < 2; half++) {
            int row = br + wm * 32 + mt * 16 + g4 + half * 8;
            if (row < M) {
#pragma unroll
                for (int nt = 0; nt < 8; nt++) {
                    int col = bc + wn * 64 + nt * 8 + (lane & 3) * 2;
                    float x0 = (acc[mt][nt][half * 2 + 0] + bias[col + 0]) * scale;
                    float x1 = (acc[mt][nt][half * 2 + 1] + bias[col + 1]) * scale;
                    if (cF) {
                        *(float2*)(cF + (size_t)row * HIDDEN + col) = make_float2(x0, x1);
                    } else if (sel == 1) {
                        unsigned short r8;
                        asm("cvt.rn.satfinite.e4m3x2.f32 %0, %1, %2;"
                            : "=h"(r8) : "f"(x1 * 16.f), "f"(x0 * 16.f));
                        *(unsigned short*)(cK8 + (size_t)row * HIDDEN + col) = r8;
                    } else {
                        __half* dstH = (sel == 0) ? cQ : cV;
                        *(__half2*)(dstH + (size_t)row * HIDDEN + col) =
                            __floats2half2_rn(x0, x1);
                    }
                }
            }
        }
    }
}

// ---------------- fused SDDMM + softmax + SPMM ----------------------------------
// Warp per node (grid 2500); lane l -> head l/4, dims l*8..l*8+7.
// K e4m3 (8B/lane), V fp16 (16B/lane). Ping-pong 4-edge pipeline: two pair
// buffers P0/P1, consumed and refilled alternately -> no rotation MOVs.
__global__ __launch_bounds__(256) void attn_kernel(const int* __restrict__ ecol) {
    const int wid = threadIdx.x >> 5, lane = threadIdx.x & 31;
    const int node = blockIdx.x * 8 + wid;

    const int start = g_rowptr[node];
    const int end = g_rowptr[node + 1];

    if (start >= end) {
        *(uint4*)(g_agg + (size_t)node * HIDDEN + lane * 8) = make_uint4(0, 0, 0, 0);
        return;
    }
    const int last = end - 1;

    uint4 qv = *((const uint4*)(g_qh + (size_t)node * HIDDEN) + lane);
    const __half2 q0 = ((const __half2*)&qv)[0];
    const __half2 q1 = ((const __half2*)&qv)[1];
    const __half2 q2 = ((const __half2*)&qv)[2];
    const __half2 q3 = ((const __half2*)&qv)[3];

    float z = 0.f;
    unsigned long long acc0 = 0ull, acc1 = 0ull, acc2 = 0ull, acc3 = 0ull;

#define LDKV(kd, vd, e)                                                     \
    do {                                                                    \
        int c_ = ecol[e];                                                   \
        kd = *((const uint2*)(g_k8 + (size_t)c_ * HIDDEN) + lane);          \
        vd = *((const uint4*)(g_vh + (size_t)c_ * HIDDEN) + lane);          \
    } while (0)

    // consume a pair of edges (eb valid, eb+1 guarded)
#define CONSUME_PAIR(kA, kB, vA, vB, eb)                                            \
    do {                                                                            \
        __half2 ka0 = e4m3x2_to_h2((kA).x), ka1 = e4m3x2_to_h2((kA).x >> 16);       \
        __half2 ka2 = e4m3x2_to_h2((kA).y), ka3 = e4m3x2_to_h2((kA).y >> 16);       \
        __half2 kb0 = e4m3x2_to_h2((kB).x), kb1 = e4m3x2_to_h2((kB).x >> 16);       \
        __half2 kb2 = e4m3x2_to_h2((kB).y), kb3 = e4m3x2_to_h2((kB).y >> 16);       \
        __half2 sa = __hmul2(q0, ka0);                                              \
        __half2 sb = __hmul2(q0, kb0);                                              \
        sa = __hfma2(q1, ka1, sa);                                                  \
        sb = __hfma2(q1, kb1, sb);                                                  \
        sa = __hfma2(q2, ka2, sa);                                                  \
        sb = __hfma2(q2, kb2, sb);                                                  \
        sa = __hfma2(q3, ka3, sa);                                                  \
        sb = __hfma2(q3, kb3, sb);                                                  \
        float pa = __low2float(sa) + __high2float(sa);                              \
        float pb = __low2float(sb) + __high2float(sb);                              \
        pa += __shfl_xor_sync(0xffffffffu, pa, 1);                                  \
        pb += __shfl_xor_sync(0xffffffffu, pb, 1);                                  \
        pa += __shfl_xor_sync(0xffffffffu, pa, 2);                                  \
        pb += __shfl_xor_sync(0xffffffffu, pb, 2);                                  \
        float wa = __expf(pa);                                                      \
        float wb = ((eb) + 1 < end) ? __expf(pb) : 0.f;                             \
        z += wa + wb;                                                               \
        unsigned long long wap = pack_dup(wa);                                      \
        unsigned long long wbp = pack_dup(wb);                                      \
        const __half2* vpa = (const __half2*)&(vA);                                 \
        const __half2* vpb = (const __half2*)&(vB);                                 \
        acc0 = fma2(wap, f2_to_ull(__half22float2(vpa[0])), acc0);                  \
        acc1 = fma2(wap, f2_to_ull(__half22float2(vpa[1])), acc1);                  \
        acc2 = fma2(wap, f2_to_ull(__half22float2(vpa[2])), acc2);                  \
        acc3 = fma2(wap, f2_to_ull(__half22float2(vpa[3])), acc3);                  \
        acc0 = fma2(wbp, f2_to_ull(__half22float2(vpb[0])), acc0);                  \
        acc1 = fma2(wbp, f2_to_ull(__half22float2(vpb[1])), acc1);                  \
        acc2 = fma2(wbp, f2_to_ull(__half22float2(vpb[2])), acc2);                  \
        acc3 = fma2(wbp, f2_to_ull(__half22float2(vpb[3])), acc3);                  \
    } while (0)

    // P0 = edges (e, e+1), P1 = edges (e+2, e+3); ping-pong refill
    uint2 k0a, k0b, k1a, k1b;
    uint4 v0a, v0b, v1a, v1b;
    LDKV(k0a, v0a, start);
    LDKV(k0b, v0b, min(start + 1, last));
    LDKV(k1a, v1a, min(start + 2, last));
    LDKV(k1b, v1b, min(start + 3, last));

    for (int e = start; e < end; e += 4) {
        CONSUME_PAIR(k0a, k0b, v0a, v0b, e);
        LDKV(k0a, v0a, min(e + 4, last));
        LDKV(k0b, v0b, min(e + 5, last));
        if (e + 2 < end) {
            CONSUME_PAIR(k1a, k1b, v1a, v1b, e + 2);
            LDKV(k1a, v1a, min(e + 6, last));
            LDKV(k1b, v1b, min(e + 7, last));
        }
    }
#undef CONSUME_PAIR
#undef LDKV

    const float inv = 1.f / z;
    float2 t0 = ull_to_f2(acc0), t1 = ull_to_f2(acc1);
    float2 t2 = ull_to_f2(acc2), t3 = ull_to_f2(acc3);
    __half o[8];
    o[0] = __float2half_rn(t0.x * inv); o[1] = __float2half_rn(t0.y * inv);
    o[2] = __float2half_rn(t1.x * inv); o[3] = __float2half_rn(t1.y * inv);
    o[4] = __float2half_rn(t2.x * inv); o[5] = __float2half_rn(t2.y * inv);
    o[6] = __float2half_rn(t3.x * inv); o[7] = __float2half_rn(t3.y * inv);
    *(uint4*)(g_agg + (size_t)node * HIDDEN + lane * 8) = *(uint4*)o;
}

// ---------------- launch --------------------------------------------------------
extern "C" void kernel_launch(void* const* d_in, const int* in_sizes, int n_in,
                              void* d_out, int out_size) {
    const int*   X    = (const int*)d_in[0];
    const int*   erow = (const int*)d_in[1];
    const int*   ecol = (const int*)d_in[2];
    const float* emb  = (const float*)d_in[3];
    const float* q_w  = (const float*)d_in[4];
    const float* q_b  = (const float*)d_in[5];
    const float* k_w  = (const float*)d_in[6];
    const float* k_b  = (const float*)d_in[7];
    const float* v_w  = (const float*)d_in[8];
    const float* v_b  = (const float*)d_in[9];
    const float* o_w  = (const float*)d_in[10];
    const float* o_b  = (const float*)d_in[11];
    float* out = (float*)d_out;

    __half *ph, *agg, *pw, *pwo, *pqh, *pvh;
    unsigned char *pk8;
    cudaGetSymbolAddress((void**)&ph,  g_h);
    cudaGetSymbolAddress((void**)&agg, g_agg);
    cudaGetSymbolAddress((void**)&pw,  g_w);
    cudaGetSymbolAddress((void**)&pwo, g_wo);
    cudaGetSymbolAddress((void**)&pqh, g_qh);
    cudaGetSymbolAddress((void**)&pk8, g_k8);
    cudaGetSymbolAddress((void**)&pvh, g_vh);

    cudaFuncSetAttribute(gemm_mma, cudaFuncAttributeMaxDynamicSharedMemorySize, SMEM_DYN);

    prep_kernel<<<(PREP_TOTAL + 255) / 256, 256>>>(emb, q_w, k_w, v_w, o_w, erow);
    embed_kernel<<<2500, 256>>>(X);

    const float qscale = 0.17677669529663687f / 16.f;   // HEAD_DIM^-0.5 / 16 (K is x16)
    gemm_mma<<<dim3(157, 6), 256, SMEM_DYN>>>(ph, pw,
                                              q_b, k_b, v_b, pqh, pk8, pvh, nullptr,
                                              qscale, N_NODES);

    attn_kernel<<<2500, 256>>>(ecol);

    gemm_mma<<<dim3(157, 2), 256, SMEM_DYN>>>(agg, pwo,
                                              o_b, o_b, o_b, nullptr, nullptr, nullptr, out,
                                              1.0f, N_NODES);
}

// round 17
// speedup vs baseline: 1.2575x; 1.0193x over previous
#include <cuda_runtime.h>
#include <cuda_bf16.h>
#include <cuda_fp16.h>
#include <cstdint>

#define N_NODES 20000
#define N_EDGES 640000
#define HIDDEN 256
#define VOCAB 119
#define N_FEATS 9
#define MPAD 20096   // 157 * 128
#define EMB_N (N_FEATS * VOCAB * HIDDEN)   // 274176
#define WN (HIDDEN * HIDDEN)               // 65536
#define N_SHARDS 64

// ---------------- scratch (device globals; zero-initialized at load) ----------
__device__ __align__(16) __half g_h[MPAD * HIDDEN];         // node features, fp16
__device__ __align__(16) __half g_agg[MPAD * HIDDEN];       // attention out, fp16
__device__ __align__(16) __half g_w[3 * WN];   // q,k,v weights fp16
__device__ __align__(16) __half g_wo[WN];      // o weights fp16
__device__ __align__(16) __half g_embh[EMB_N]; // fp16 embedding tables
__device__ __align__(16) __half g_qh[MPAD * HIDDEN];        // fp16 Q (pre-scaled /16)
__device__ __align__(16) unsigned char g_k8[MPAD * HIDDEN]; // e4m3 K (x16)
__device__ __align__(16) __half g_vh[MPAD * HIDDEN];
__device__ int g_rowptr[N_NODES + 1];
__device__ unsigned g_ctr[N_SHARDS];          // work-stealing counters (reset in prep)

// ---------------- PTX helpers ---------------------------------------------------
__device__ __forceinline__ uint32_t smem_u32(const void* p) {
    uint32_t a;
    asm("{ .reg .u64 t; cvta.to.shared.u64 t, %1; cvt.u32.u64 %0, t; }" : "=r"(a) : "l"(p));
    return a;
}
__device__ __forceinline__ void mma16816(float* d, const uint32_t* a,
                                         uint32_t b0, uint32_t b1) {
    asm volatile(
        "mma.sync.aligned.m16n8k16.row.col.f32.f16.f16.f32 "
        "{%0,%1,%2,%3}, {%4,%5,%6,%7}, {%8,%9}, {%0,%1,%2,%3};"
        : "+f"(d[0]), "+f"(d[1]), "+f"(d[2]), "+f"(d[3])
        : "r"(a[0]), "r"(a[1]), "r"(a[2]), "r"(a[3]), "r"(b0), "r"(b1));
}
__device__ __forceinline__ void ldm_x4(uint32_t* r, uint32_t addr) {
    asm volatile("ldmatrix.sync.aligned.m8n8.x4.shared.b16 {%0,%1,%2,%3}, [%4];"
                 : "=r"(r[0]), "=r"(r[1]), "=r"(r[2]), "=r"(r[3]) : "r"(addr));
}
__device__ __forceinline__ unsigned long long pack_dup(float x) {
    unsigned long long r;
    asm("mov.b64 %0, {%1, %1};" : "=l"(r) : "f"(x));
    return r;
}
__device__ __forceinline__ unsigned long long f2_to_ull(float2 v) {
    unsigned long long r;
    asm("mov.b64 %0, {%1, %2};" : "=l"(r) : "f"(v.x), "f"(v.y));
    return r;
}
__device__ __forceinline__ float2 ull_to_f2(unsigned long long v) {
    float2 r;
    asm("mov.b64 {%0, %1}, %2;" : "=f"(r.x), "=f"(r.y) : "l"(v));
    return r;
}
__device__ __forceinline__ unsigned long long fma2(unsigned long long a,
                                                   unsigned long long b,
                                                   unsigned long long c) {
    unsigned long long d;
    asm("fma.rn.f32x2 %0, %1, %2, %3;" : "=l"(d) : "l"(a), "l"(b), "l"(c));
    return d;
}
__device__ __forceinline__ __half2 e4m3x2_to_h2(uint32_t v) {
    uint32_t r;
    asm("cvt.rn.f16x2.e4m3x2 %0, %1;" : "=r"(r) : "h"((unsigned short)v));
    return *(__half2*)&r;
}
#define CP16(dst, src) \
    asm volatile("cp.async.cg.shared.global [%0], [%1], 16;" :: "r"(dst), "l"(src))
#define CP_COMMIT() asm volatile("cp.async.commit_group;" ::: "memory")
#define CP_WAIT0()  asm volatile("cp.async.wait_group 0;" ::: "memory")

// ---------------- fused prep (4-wide): emb cvt + weight cvts + rowptr + ctrs ----
#define PREP_VEC ((EMB_N + 4 * WN) / 4)
#define PREP_TOTAL (PREP_VEC + N_NODES + 1 + N_SHARDS)

__global__ void prep_kernel(const float* __restrict__ emb,
                            const float* __restrict__ qw, const float* __restrict__ kw,
                            const float* __restrict__ vw, const float* __restrict__ ow,
                            const int* __restrict__ erow) {
    int i = blockIdx.x * 256 + threadIdx.x;
    if (i < PREP_VEC) {
        const int j = i * 4;
        const float* src;
        __half* dst;
        if (j < EMB_N) {
            src = emb + j;
            dst = g_embh + j;
        } else {
            const int k = j - EMB_N;
            const int seg = k >> 16, jj = k & (WN - 1);
            src = ((seg == 0) ? qw : (seg == 1) ? kw : (seg == 2) ? vw : ow) + jj;
            dst = (seg == 3) ? (g_wo + jj) : (g_w + k);
        }
        float4 x = *(const float4*)src;
        __half h[4];
        h[0] = __float2half_rn(x.x);
        h[1] = __float2half_rn(x.y);
        h[2] = __float2half_rn(x.z);
        h[3] = __float2half_rn(x.w);
        *(uint2*)dst = *(uint2*)h;
        return;
    }
    i -= PREP_VEC;
    if (i <= N_NODES) {
        int lo = 0, hi = N_EDGES;
        while (lo < hi) {
            int mid = (lo + hi) >> 1;
            if (erow[mid] < i) lo = mid + 1; else hi = mid;
        }
        g_rowptr[i] = lo;
        return;
    }
    i -= N_NODES + 1;
    if (i < N_SHARDS) g_ctr[i] = 0;
}

// ---------------- AtomEncoder: warp per node, uint4 gathers ---------------------
__global__ __launch_bounds__(256) void embed_kernel(const int* __restrict__ X) {
    const int wid = threadIdx.x >> 5, lane = threadIdx.x & 31;
    const int node = blockIdx.x * 8 + wid;
    int xi = (lane < N_FEATS) ? X[node * N_FEATS + lane] : 0;

    float acc[8];
#pragma unroll
    for (int j = 0; j < 8; j++) acc[j] = 0.f;
#pragma unroll
    for (int f = 0; f < N_FEATS; f++) {
        int idx = __shfl_sync(0xffffffffu, xi, f);
        uint4 t = *((const uint4*)(g_embh + (size_t)(f * VOCAB + idx) * HIDDEN) + lane);
        const __half2* tp = (const __half2*)&t;
#pragma unroll
        for (int h = 0; h < 4; h++) {
            float2 x = __half22float2(tp[h]);
            acc[2 * h + 0] += x.x;
            acc[2 * h + 1] += x.y;
        }
    }
    __half hv[8];
#pragma unroll
    for (int j = 0; j < 8; j++) hv[j] = __float2half_rn(acc[j]);
    *(uint4*)(g_h + (size_t)node * HIDDEN + lane * 8) = *(uint4*)hv;
}

// ---------------- HMMA GEMM: single-pass fp16, 64-K chunks, 1 sync/chunk --------
#define RSTRIDE 144
#define TILE_B (128 * RSTRIDE)          // 18432
#define BUF_B  (2 * TILE_B)             // 36864: A, B
#define SMEM_DYN (2 * BUF_B)            // 73728

__global__ __launch_bounds__(256, 2) void gemm_mma(
    const __half* __restrict__ A, const __half* __restrict__ W,
    const float* __restrict__ b0, const float* __restrict__ b1, const float* __restrict__ b2,
    __half* __restrict__ cQ, unsigned char* __restrict__ cK8, __half* __restrict__ cV,
    float* __restrict__ cF,
    float scaleQ, int M)
{
    extern __shared__ __align__(16) char sm[];
    const uint32_t sbase = smem_u32(sm);

    const int tid = threadIdx.x;
    const int wid = tid >> 5, lane = tid & 31;
    const int br = blockIdx.x * 128;
    const int sel = blockIdx.y >> 1;
    const int bc = (blockIdx.y & 1) * 128;
    const int wm = wid & 3, wn = wid >> 2;

    float acc[2][8][4];
#pragma unroll
    for (int mt = 0; mt < 2; mt++)
#pragma unroll
        for (int nt = 0; nt < 8; nt++)
#pragma unroll
            for (int i = 0; i < 4; i++) acc[mt][nt][i] = 0.f;

    const char* gA = (const char*)(A + (size_t)br * HIDDEN);
    const char* gB = (const char*)(W + (size_t)sel * WN + (size_t)bc * HIDDEN);

    const int rI[4] = {tid >> 3, (tid + 256) >> 3, (tid + 512) >> 3, (tid + 768) >> 3};
    const int uI    = tid & 7;

#define LOAD_CHUNK(ch, buf)                                                         \
    do {                                                                            \
        uint32_t sb_ = sbase + (buf) * BUF_B;                                       \
        _Pragma("unroll")                                                           \
        for (int s_ = 0; s_ < 4; s_++) {                                            \
            uint32_t so_ = (uint32_t)(rI[s_] * RSTRIDE + uI * 16);                  \
            size_t go_ = (size_t)rI[s_] * 512 + (ch) * 128 + uI * 16;               \
            CP16(sb_ + so_,          gA + go_);                                     \
            CP16(sb_ + TILE_B + so_, gB + go_);                                     \
        }                                                                           \
    } while (0)

    LOAD_CHUNK(0, 0);
    CP_COMMIT();

    const uint32_t aRow = (uint32_t)(wm * 32 + (lane & 15));
    const uint32_t aKoff = (uint32_t)((lane >> 4) << 4);
    const uint32_t bRow = (uint32_t)(wn * 64 + (lane & 7) + ((lane >> 4) << 3));
    const uint32_t bKoff = (uint32_t)(((lane >> 3) & 1) << 4);

    for (int ch = 0; ch < 4; ch++) {
        CP_WAIT0();
        __syncthreads();
        if (ch + 1 < 4) {
            LOAD_CHUNK(ch + 1, (ch + 1) & 1);
            CP_COMMIT();
        }
        const uint32_t sb = sbase + (ch & 1) * BUF_B;
#pragma unroll
        for (int ks = 0; ks < 4; ks++) {
            const uint32_t ko = ks * 32;
            uint32_t ah[2][4];
#pragma unroll
            for (int mt = 0; mt < 2; mt++) {
                uint32_t arow = (aRow + mt * 16) * RSTRIDE + ko + aKoff;
                ldm_x4(ah[mt], sb + arow);
            }
#pragma unroll
            for (int g = 0; g < 4; g++) {
                uint32_t brow = (bRow + g * 16) * RSTRIDE + ko + bKoff;
                uint32_t bm[4];
                ldm_x4(bm, sb + TILE_B + brow);
#pragma unroll
                for (int t = 0; t < 2; t++) {
                    const int nt = g * 2 + t;
#pragma unroll
                    for (int mt = 0; mt < 2; mt++)
                        mma16816(acc[mt][nt], ah[mt], bm[2 * t], bm[2 * t + 1]);
                }
            }
        }
    }
#undef LOAD_CHUNK

    // epilogue
    const float* bias = (sel == 0) ? b0 : (sel == 1) ? b1 : b2;
    const float scale = (sel == 0) ? scaleQ : 1.0f;
    const int g4 = lane >> 2;
#pragma unroll
    for (int mt = 0; mt < 2; mt++) {
#pragma unroll
        for (int half = 0; half < 2; half++) {
            int row = br + wm * 32 + mt * 16 + g4 + half * 8;
            if (row < M) {
#pragma unroll
                for (int nt = 0; nt < 8; nt++) {
                    int col = bc + wn * 64 + nt * 8 + (lane & 3) * 2;
                    float x0 = (acc[mt][nt][half * 2 + 0] + bias[col + 0]) * scale;
                    float x1 = (acc[mt][nt][half * 2 + 1] + bias[col + 1]) * scale;
                    if (cF) {
                        *(float2*)(cF + (size_t)row * HIDDEN + col) = make_float2(x0, x1);
                    } else if (sel == 1) {
                        unsigned short r8;
                        asm("cvt.rn.satfinite.e4m3x2.f32 %0, %1, %2;"
                            : "=h"(r8) : "f"(x1 * 16.f), "f"(x0 * 16.f));
                        *(unsigned short*)(cK8 + (size_t)row * HIDDEN + col) = r8;
                    } else {
                        __half* dstH = (sel == 0) ? cQ : cV;
                        *(__half2*)(dstH + (size_t)row * HIDDEN + col) =
                            __floats2half2_rn(x0, x1);
                    }
                }
            }
        }
    }
}

// ---------------- fused SDDMM + softmax + SPMM ----------------------------------
// Persistent warps + sharded work stealing. Shard = gw & 63 owns a ~313-node
// range; each warp steals one node at a time (atomic per node, ~0.05/cyc/ctr).
// Per-node body identical to R16: lane l -> head l/4, dims l*8..l*8+7,
// K e4m3, V fp16, ping-pong 4-edge pipeline.
__global__ __launch_bounds__(256) void attn_kernel(const int* __restrict__ ecol) {
    const int wid = threadIdx.x >> 5, lane = threadIdx.x & 31;
    const int gw = blockIdx.x * 8 + wid;
    const int shard = gw & (N_SHARDS - 1);
    const int s0 = (shard * N_NODES) >> 6;
    const int s1 = ((shard + 1) * N_NODES) >> 6;

    for (;;) {
        int node = 0;
        if (lane == 0) node = s0 + (int)atomicAdd(&g_ctr[shard], 1u);
        node = __shfl_sync(0xffffffffu, node, 0);
        if (node >= s1) break;

        const int start = g_rowptr[node];
        const int end = g_rowptr[node + 1];

        if (start >= end) {
            *(uint4*)(g_agg + (size_t)node * HIDDEN + lane * 8) = make_uint4(0, 0, 0, 0);
            continue;
        }
        const int last = end - 1;

        uint4 qv = *((const uint4*)(g_qh + (size_t)node * HIDDEN) + lane);
        const __half2 q0 = ((const __half2*)&qv)[0];
        const __half2 q1 = ((const __half2*)&qv)[1];
        const __half2 q2 = ((const __half2*)&qv)[2];
        const __half2 q3 = ((const __half2*)&qv)[3];

        float z = 0.f;
        unsigned long long acc0 = 0ull, acc1 = 0ull, acc2 = 0ull, acc3 = 0ull;

#define LDKV(kd, vd, e)                                                     \
        do {                                                                \
            int c_ = ecol[e];                                               \
            kd = *((const uint2*)(g_k8 + (size_t)c_ * HIDDEN) + lane);      \
            vd = *((const uint4*)(g_vh + (size_t)c_ * HIDDEN) + lane);      \
        } while (0)

#define CONSUME_PAIR(kA, kB, vA, vB, eb)                                            \
        do {                                                                        \
            __half2 ka0 = e4m3x2_to_h2((kA).x), ka1 = e4m3x2_to_h2((kA).x >> 16);   \
            __half2 ka2 = e4m3x2_to_h2((kA).y), ka3 = e4m3x2_to_h2((kA).y >> 16);   \
            __half2 kb0 = e4m3x2_to_h2((kB).x), kb1 = e4m3x2_to_h2((kB).x >> 16);   \
            __half2 kb2 = e4m3x2_to_h2((kB).y), kb3 = e4m3x2_to_h2((kB).y >> 16);   \
            __half2 sa = __hmul2(q0, ka0);                                          \
            __half2 sb = __hmul2(q0, kb0);                                          \
            sa = __hfma2(q1, ka1, sa);                                              \
            sb = __hfma2(q1, kb1, sb);                                              \
            sa = __hfma2(q2, ka2, sa);                                              \
            sb = __hfma2(q2, kb2, sb);                                              \
            sa = __hfma2(q3, ka3, sa);                                              \
            sb = __hfma2(q3, kb3, sb);                                              \
            float pa = __low2float(sa) + __high2float(sa);                          \
            float pb = __low2float(sb) + __high2float(sb);                          \
            pa += __shfl_xor_sync(0xffffffffu, pa, 1);                              \
            pb += __shfl_xor_sync(0xffffffffu, pb, 1);                              \
            pa += __shfl_xor_sync(0xffffffffu, pa, 2);                              \
            pb += __shfl_xor_sync(0xffffffffu, pb, 2);                              \
            float wa = __expf(pa);                                                  \
            float wb = ((eb) + 1 < end) ? __expf(pb) : 0.f;                         \
            z += wa + wb;                                                           \
            unsigned long long wap = pack_dup(wa);                                  \
            unsigned long long wbp = pack_dup(wb);                                  \
            const __half2* vpa = (const __half2*)&(vA);                             \
            const __half2* vpb = (const __half2*)&(vB);                             \
            acc0 = fma2(wap, f2_to_ull(__half22float2(vpa[0])), acc0);              \
            acc1 = fma2(wap, f2_to_ull(__half22float2(vpa[1])), acc1);              \
            acc2 = fma2(wap, f2_to_ull(__half22float2(vpa[2])), acc2);              \
            acc3 = fma2(wap, f2_to_ull(__half22float2(vpa[3])), acc3);              \
            acc0 = fma2(wbp, f2_to_ull(__half22float2(vpb[0])), acc0);              \
            acc1 = fma2(wbp, f2_to_ull(__half22float2(vpb[1])), acc1);              \
            acc2 = fma2(wbp, f2_to_ull(__half22float2(vpb[2])), acc2);              \
            acc3 = fma2(wbp, f2_to_ull(__half22float2(vpb[3])), acc3);              \
        } while (0)

        uint2 k0a, k0b, k1a, k1b;
        uint4 v0a, v0b, v1a, v1b;
        LDKV(k0a, v0a, start);
        LDKV(k0b, v0b, min(start + 1, last));
        LDKV(k1a, v1a, min(start + 2, last));
        LDKV(k1b, v1b, min(start + 3, last));

        for (int e = start; e < end; e += 4) {
            CONSUME_PAIR(k0a, k0b, v0a, v0b, e);
            LDKV(k0a, v0a, min(e + 4, last));
            LDKV(k0b, v0b, min(e + 5, last));
            if (e + 2 < end) {
                CONSUME_PAIR(k1a, k1b, v1a, v1b, e + 2);
                LDKV(k1a, v1a, min(e + 6, last));
                LDKV(k1b, v1b, min(e + 7, last));
            }
        }
#undef CONSUME_PAIR
#undef LDKV

        const float inv = 1.f / z;
        float2 t0 = ull_to_f2(acc0), t1 = ull_to_f2(acc1);
        float2 t2 = ull_to_f2(acc2), t3 = ull_to_f2(acc3);
        __half o[8];
        o[0] = __float2half_rn(t0.x * inv); o[1] = __float2half_rn(t0.y * inv);
        o[2] = __float2half_rn(t1.x * inv); o[3] = __float2half_rn(t1.y * inv);
        o[4] = __float2half_rn(t2.x * inv); o[5] = __float2half_rn(t2.y * inv);
        o[6] = __float2half_rn(t3.x * inv); o[7] = __float2half_rn(t3.y * inv);
        *(uint4*)(g_agg + (size_t)node * HIDDEN + lane * 8) = *(uint4*)o;
    }
}

// ---------------- launch --------------------------------------------------------
extern "C" void kernel_launch(void* const* d_in, const int* in_sizes, int n_in,
                              void* d_out, int out_size) {
    const int*   X    = (const int*)d_in[0];
    const int*   erow = (const int*)d_in[1];
    const int*   ecol = (const int*)d_in[2];
    const float* emb  = (const float*)d_in[3];
    const float* q_w  = (const float*)d_in[4];
    const float* q_b  = (const float*)d_in[5];
    const float* k_w  = (const float*)d_in[6];
    const float* k_b  = (const float*)d_in[7];
    const float* v_w  = (const float*)d_in[8];
    const float* v_b  = (const float*)d_in[9];
    const float* o_w  = (const float*)d_in[10];
    const float* o_b  = (const float*)d_in[11];
    float* out = (float*)d_out;

    __half *ph, *agg, *pw, *pwo, *pqh, *pvh;
    unsigned char *pk8;
    cudaGetSymbolAddress((void**)&ph,  g_h);
    cudaGetSymbolAddress((void**)&agg, g_agg);
    cudaGetSymbolAddress((void**)&pw,  g_w);
    cudaGetSymbolAddress((void**)&pwo, g_wo);
    cudaGetSymbolAddress((void**)&pqh, g_qh);
    cudaGetSymbolAddress((void**)&pk8, g_k8);
    cudaGetSymbolAddress((void**)&pvh, g_vh);

    cudaFuncSetAttribute(gemm_mma, cudaFuncAttributeMaxDynamicSharedMemorySize, SMEM_DYN);

    prep_kernel<<<(PREP_TOTAL + 255) / 256, 256>>>(emb, q_w, k_w, v_w, o_w, erow);
    embed_kernel<<<2500, 256>>>(X);

    const float qscale = 0.17677669529663687f / 16.f;   // HEAD_DIM^-0.5 / 16 (K is x16)
    gemm_mma<<<dim3(157, 6), 256, SMEM_DYN>>>(ph, pw,
                                              q_b, k_b, v_b, pqh, pk8, pvh, nullptr,
                                              qscale, N_NODES);

    attn_kernel<<<592, 256>>>(ecol);

    gemm_mma<<<dim3(157, 2), 256, SMEM_DYN>>>(agg, pwo,
                                              o_b, o_b, o_b, nullptr, nullptr, nullptr, out,
                                              1.0f, N_NODES);
}